// round 13
// baseline (speedup 1.0000x reference)
#include <cuda_runtime.h>
#include <cuda_bf16.h>
#include <cstdint>

// Problem dims
#define MTOT 8192      // B*T
#define KDIM 4096      // D_IN
#define NDIM 16384     // D_OUT

// GEMM tiling (bf16 operands)
#define TILE_M 128
#define TILE_N 128
#define KC 64                       // bf16 elements per K chunk (128 B/row)
#define NK (KDIM / KC)              // 64
#define STAGES 3
#define ROWB 128                    // bytes per tile row in smem
#define STAGE_A_BYTES (TILE_M * ROWB)                 // 16KB
#define STAGE_BYTES (STAGE_A_BYTES + TILE_N * ROWB)   // 32KB
#define SMEM_TOTAL (STAGES * STAGE_BYTES)             // 96KB
#define GEMM_THREADS 256

#define NTILES_M (MTOT / TILE_M)    // 64
#define NTILES_N (NDIM / TILE_N)    // 128
#define GROUP_M 16

// ---------------------------------------------------------------------------
// Scratch (device globals; no allocation allowed)
// ---------------------------------------------------------------------------
__device__ __align__(16) __nv_bfloat16 g_Xq[(size_t)MTOT * KDIM];   // 64 MB
__device__ __align__(16) __nv_bfloat16 g_Wq[(size_t)NDIM * KDIM];   // 128 MB
__device__ float g_scale[MTOT];
__device__ float g_partial[2048];
__device__ float g_wscale;

// ---------------------------------------------------------------------------
// PTX helpers (portable compute_103 features only)
// ---------------------------------------------------------------------------
__device__ __forceinline__ uint32_t smem_u32(const void* p) {
    uint32_t a;
    asm("{ .reg .u64 t; cvta.to.shared.u64 t, %1; cvt.u32.u64 %0, t; }" : "=r"(a) : "l"(p));
    return a;
}

__device__ __forceinline__ void cp_async16(uint32_t dst, const void* src) {
    asm volatile("cp.async.cg.shared.global [%0], [%1], 16;" :: "r"(dst), "l"(src) : "memory");
}
__device__ __forceinline__ void cp_async_commit() {
    asm volatile("cp.async.commit_group;" ::: "memory");
}
template <int N>
__device__ __forceinline__ void cp_async_wait() {
    asm volatile("cp.async.wait_group %0;" :: "n"(N) : "memory");
}

__device__ __forceinline__ void ldmatrix_x4(uint32_t* r, uint32_t addr) {
    asm volatile("ldmatrix.sync.aligned.m8n8.x4.shared.b16 {%0,%1,%2,%3}, [%4];"
                 : "=r"(r[0]), "=r"(r[1]), "=r"(r[2]), "=r"(r[3]) : "r"(addr));
}

__device__ __forceinline__ void mma_bf16(float* d, const uint32_t* a, uint32_t b0, uint32_t b1) {
    asm volatile(
        "mma.sync.aligned.m16n8k16.row.col.f32.bf16.bf16.f32 "
        "{%0,%1,%2,%3}, {%4,%5,%6,%7}, {%8,%9}, {%0,%1,%2,%3};"
        : "+f"(d[0]), "+f"(d[1]), "+f"(d[2]), "+f"(d[3])
        : "r"(a[0]), "r"(a[1]), "r"(a[2]), "r"(a[3]), "r"(b0), "r"(b1));
}

// ---------------------------------------------------------------------------
// Kernel 1 (fused): blocks [0, MTOT) quantize X rows; blocks [MTOT, MTOT+2048)
// compute the deterministic partial sums of |W|. Independent work, one launch,
// so both DRAM-bound phases overlap on the chip.
// ---------------------------------------------------------------------------
__global__ void __launch_bounds__(256) fused_qx_wabs_kernel(
    const float* __restrict__ x, const float* __restrict__ w) {
    __shared__ float red[256];
    __shared__ float wmax[8];
    __shared__ float s_scale;
    const int tid = threadIdx.x;

    if (blockIdx.x < MTOT) {
        // ---- per-token activation quantization -> bf16 integer (exact) ----
        const int row = blockIdx.x;
        const float4* xr = reinterpret_cast<const float4*>(x) + (size_t)row * (KDIM / 4);
        float4 v[4];
        float amax = 0.0f;
#pragma unroll
        for (int i = 0; i < 4; i++) {
            v[i] = xr[tid + i * 256];
            amax = fmaxf(amax, fmaxf(fmaxf(fabsf(v[i].x), fabsf(v[i].y)),
                                     fmaxf(fabsf(v[i].z), fabsf(v[i].w))));
        }
#pragma unroll
        for (int o = 16; o; o >>= 1) amax = fmaxf(amax, __shfl_xor_sync(0xffffffffu, amax, o));
        if ((tid & 31) == 0) wmax[tid >> 5] = amax;
        __syncthreads();
        if (tid == 0) {
            float m = wmax[0];
#pragma unroll
            for (int i = 1; i < 8; i++) m = fmaxf(m, wmax[i]);
            float sc = m / 127.0f;
            s_scale = sc;
            g_scale[row] = sc;
        }
        __syncthreads();
        const float d = s_scale + 1e-8f;
        ushort4* qr = reinterpret_cast<ushort4*>(g_Xq + (size_t)row * KDIM);
#pragma unroll
        for (int i = 0; i < 4; i++) {
            float q0 = fminf(fmaxf(rintf(v[i].x / d), -128.0f), 127.0f);
            float q1 = fminf(fmaxf(rintf(v[i].y / d), -128.0f), 127.0f);
            float q2 = fminf(fmaxf(rintf(v[i].z / d), -128.0f), 127.0f);
            float q3 = fminf(fmaxf(rintf(v[i].w / d), -128.0f), 127.0f);
            ushort4 u;
            u.x = __bfloat16_as_ushort(__float2bfloat16(q0));
            u.y = __bfloat16_as_ushort(__float2bfloat16(q1));
            u.z = __bfloat16_as_ushort(__float2bfloat16(q2));
            u.w = __bfloat16_as_ushort(__float2bfloat16(q3));
            qr[tid + i * 256] = u;
        }
    } else {
        // ---- deterministic partial sums of |W| (unchanged arithmetic) ----
        const int blk = blockIdx.x - MTOT;
        const float4* wp = reinterpret_cast<const float4*>(w);
        size_t base = (size_t)blk * 8192;
        float s = 0.0f;
#pragma unroll 8
        for (int i = 0; i < 32; i++) {
            float4 v = wp[base + tid + (size_t)i * 256];
            s += fabsf(v.x) + fabsf(v.y) + fabsf(v.z) + fabsf(v.w);
        }
        red[tid] = s;
        __syncthreads();
        for (int o = 128; o; o >>= 1) {
            if (tid < o) red[tid] += red[tid + o];
            __syncthreads();
        }
        if (tid == 0) g_partial[blk] = red[0];
    }
}

__global__ void __launch_bounds__(256) wabs_final_kernel() {
    __shared__ float red[256];
    const int tid = threadIdx.x;
    float s = 0.0f;
#pragma unroll
    for (int i = 0; i < 8; i++) s += g_partial[tid * 8 + i];
    red[tid] = s;
    __syncthreads();
    for (int o = 128; o; o >>= 1) {
        if (tid < o) red[tid] += red[tid + o];
        __syncthreads();
    }
    if (tid == 0) g_wscale = red[0] / (float)((size_t)NDIM * KDIM);
}

// ---------------------------------------------------------------------------
// Kernel 2c: ternary weight quantization -> bf16 {-1,0,1}
// ---------------------------------------------------------------------------
__global__ void __launch_bounds__(256) quant_w_kernel(const float* __restrict__ w) {
    const float thr = 0.5f * (g_wscale + 1e-8f);
    const int tid = threadIdx.x;
    const float4* wp = reinterpret_cast<const float4*>(w);
    ushort4* qp = reinterpret_cast<ushort4*>(g_Wq);
    const unsigned short POS = __bfloat16_as_ushort(__float2bfloat16(1.0f));
    const unsigned short NEG = __bfloat16_as_ushort(__float2bfloat16(-1.0f));
#pragma unroll
    for (int i = 0; i < 4; i++) {
        size_t j = (size_t)blockIdx.x * 1024 + tid + i * 256;
        float4 v = wp[j];
        ushort4 u;
        u.x = (fabsf(v.x) > thr) ? (v.x > 0.0f ? POS : NEG) : 0;
        u.y = (fabsf(v.y) > thr) ? (v.y > 0.0f ? POS : NEG) : 0;
        u.z = (fabsf(v.z) > thr) ? (v.z > 0.0f ? POS : NEG) : 0;
        u.w = (fabsf(v.w) > thr) ? (v.w > 0.0f ? POS : NEG) : 0;
        qp[j] = u;
    }
}

// ---------------------------------------------------------------------------
// Kernel 3: bf16 HMMA mma.sync GEMM, 3-stage cp.async pipeline, SW swizzle.
// CTA tile 128x128, 8 warps (2m x 4n), warp tile 64x32, 2 CTAs/SM.
// ks=0 operand loads hoisted above the cp.async issue of the next stage.
// ---------------------------------------------------------------------------
__global__ void __launch_bounds__(GEMM_THREADS, 2) bitlinear_gemm_kernel(
    const float* __restrict__ bias, float* __restrict__ out) {
    extern __shared__ char smem[];
    const uint32_t sbase = smem_u32(smem);
    const int tid = threadIdx.x;

    // tile swizzle for L2 reuse
    const int pid = blockIdx.x;
    const int group = pid / (GROUP_M * NTILES_N);
    const int pig = pid % (GROUP_M * NTILES_N);
    const int pm = group * GROUP_M + (pig % GROUP_M);
    const int pn = pig / GROUP_M;
    const int m0 = pm * TILE_M;
    const int n0 = pn * TILE_N;

    const __nv_bfloat16* gA = g_Xq + (size_t)m0 * KDIM;
    const __nv_bfloat16* gB = g_Wq + (size_t)n0 * KDIM;

    // consumer (ldmatrix) lane constants
    const int wid = tid >> 5;
    const int lane = tid & 31;
    const int wm = (wid & 1) * 64;       // warp m offset (2 warps in m)
    const int wn = (wid >> 1) * 32;      // warp n offset (4 warps in n)
    const int lr = lane & 7;             // row within 8-row tile
    const int lt = lane >> 3;            // which of 4 ldmatrix tiles
    const int a_row = wm + (lt & 1) * 8 + lr;          // + mi*16
    const int a_colb = (lt >> 1) * 16;                 // + ks*32, then ^ (lr<<4)
    const int b_row = wn + (lt >> 1) * 8 + lr;         // + g*16
    const int b_colb = (lt & 1) * 16;                  // + ks*32, then ^ (lr<<4)
    const int lxor = lr << 4;

    float d[4][4][4];
#pragma unroll
    for (int mi = 0; mi < 4; mi++)
#pragma unroll
        for (int ni = 0; ni < 4; ni++)
#pragma unroll
            for (int r = 0; r < 4; r++) d[mi][ni][r] = 0.0f;

    // -------- producer: 2048 16B segments per stage, 8 per thread --------
    auto issue_stage = [&](int kc, int buf) {
        const uint32_t stage = sbase + buf * STAGE_BYTES;
        const int koff = kc * KC;   // element offset
#pragma unroll
        for (int i = 0; i < 8; i++) {
            const int idx = tid + i * GEMM_THREADS;
            const int j = idx & 1023;
            const int row = j >> 3;
            const int c = j & 7;
            const uint32_t swb = (uint32_t)((c << 4) ^ ((row & 7) << 4));
            if (idx < 1024) {
                cp_async16(stage + row * ROWB + swb,
                           gA + (size_t)row * KDIM + koff + (c << 3));
            } else {
                cp_async16(stage + STAGE_A_BYTES + row * ROWB + swb,
                           gB + (size_t)row * KDIM + koff + (c << 3));
            }
        }
    };

    // ldmatrix loader for one ks step (order: first-consumed operands first)
    auto load_ops = [&](uint32_t sA, uint32_t sB, int ks, uint32_t a[4][4], uint32_t b[2][4]) {
        {
            uint32_t addr = sA + (uint32_t)(a_row + 0 * 16) * ROWB
                          + (uint32_t)((a_colb + ks * 32) ^ lxor);
            ldmatrix_x4(a[0], addr);
        }
        {
            uint32_t addr = sB + (uint32_t)(b_row + 0 * 16) * ROWB
                          + (uint32_t)((b_colb + ks * 32) ^ lxor);
            ldmatrix_x4(b[0], addr);
        }
        {
            uint32_t addr = sB + (uint32_t)(b_row + 1 * 16) * ROWB
                          + (uint32_t)((b_colb + ks * 32) ^ lxor);
            ldmatrix_x4(b[1], addr);
        }
#pragma unroll
        for (int mi = 1; mi < 4; mi++) {
            uint32_t addr = sA + (uint32_t)(a_row + mi * 16) * ROWB
                          + (uint32_t)((a_colb + ks * 32) ^ lxor);
            ldmatrix_x4(a[mi], addr);
        }
    };

    // prologue: stages 0,1
    issue_stage(0, 0); cp_async_commit();
    issue_stage(1, 1); cp_async_commit();

    int buf = 0;
    for (int kc = 0; kc < NK; kc++) {
        cp_async_wait<1>();
        __syncthreads();

        const uint32_t sA = sbase + buf * STAGE_BYTES;
        const uint32_t sB = sA + STAGE_A_BYTES;

        // operands for ks=0 start loading before the cp.async issue burst
        uint32_t a[4][4];
        uint32_t b[2][4];
        load_ops(sA, sB, 0, a, b);

        // issue next-next stage (into buffer freed last iteration)
        if (kc + 2 < NK) {
            int nbuf = buf + 2; if (nbuf >= STAGES) nbuf -= STAGES;
            issue_stage(kc + 2, nbuf);
        }
        cp_async_commit();

#pragma unroll
        for (int ks = 0; ks < 4; ks++) {
#pragma unroll
            for (int mi = 0; mi < 4; mi++)
#pragma unroll
                for (int ni = 0; ni < 4; ni++)
                    mma_bf16(d[mi][ni], a[mi], b[ni >> 1][(ni & 1) * 2],
                             b[ni >> 1][(ni & 1) * 2 + 1]);
            if (ks < 3) load_ops(sA, sB, ks + 1, a, b);
        }
        if (++buf == STAGES) buf = 0;
    }

    // -------- epilogue: out = scale[m]*acc + bias[n] --------
#pragma unroll
    for (int mi = 0; mi < 4; mi++) {
        const int m_lo = m0 + wm + mi * 16 + (lane >> 2);
        const float sc0 = g_scale[m_lo];
        const float sc1 = g_scale[m_lo + 8];
#pragma unroll
        for (int ni = 0; ni < 4; ni++) {
            const int n = n0 + wn + ni * 8 + 2 * (lane & 3);
            const float2 bs = *reinterpret_cast<const float2*>(bias + n);
            float2 v0, v1;
            v0.x = fmaf(sc0, d[mi][ni][0], bs.x);
            v0.y = fmaf(sc0, d[mi][ni][1], bs.y);
            v1.x = fmaf(sc1, d[mi][ni][2], bs.x);
            v1.y = fmaf(sc1, d[mi][ni][3], bs.y);
            *reinterpret_cast<float2*>(out + (size_t)m_lo * NDIM + n) = v0;
            *reinterpret_cast<float2*>(out + (size_t)(m_lo + 8) * NDIM + n) = v1;
        }
    }
}

// ---------------------------------------------------------------------------
// Launch
// ---------------------------------------------------------------------------
extern "C" void kernel_launch(void* const* d_in, const int* in_sizes, int n_in,
                              void* d_out, int out_size) {
    const float* x = (const float*)d_in[0];
    const float* w = (const float*)d_in[1];
    const float* bias = (const float*)d_in[2];
    float* out = (float*)d_out;

    cudaFuncSetAttribute(bitlinear_gemm_kernel,
                         cudaFuncAttributeMaxDynamicSharedMemorySize, SMEM_TOTAL);

    fused_qx_wabs_kernel<<<MTOT + 2048, 256>>>(x, w);
    wabs_final_kernel<<<1, 256>>>();
    quant_w_kernel<<<16384, 256>>>(w);

    const int grid = NTILES_M * NTILES_N;   // 64 * 128 = 8192
    bitlinear_gemm_kernel<<<grid, GEMM_THREADS, SMEM_TOTAL>>>(bias, out);
}

// round 15
// speedup vs baseline: 1.0984x; 1.0984x over previous
#include <cuda_runtime.h>
#include <cuda_bf16.h>
#include <cstdint>

// Problem dims
#define MTOT 8192      // B*T
#define KDIM 4096      // D_IN
#define NDIM 16384     // D_OUT

// GEMM tiling (bf16 operands)
#define TILE_M 128
#define TILE_N 128
#define KC 64                       // bf16 elements per K chunk (128 B/row)
#define NK (KDIM / KC)              // 64
#define STAGES 3
#define ROWB 128                    // bytes per tile row in smem
#define STAGE_A_BYTES (TILE_M * ROWB)                 // 16KB
#define STAGE_BYTES (STAGE_A_BYTES + TILE_N * ROWB)   // 32KB
#define SMEM_TOTAL (STAGES * STAGE_BYTES)             // 96KB
#define GEMM_THREADS 256

#define NTILES_M (MTOT / TILE_M)    // 64
#define NTILES_N (NDIM / TILE_N)    // 128
#define GROUP_M 16

// ---------------------------------------------------------------------------
// Scratch (device globals; no allocation allowed)
// ---------------------------------------------------------------------------
__device__ __align__(16) __nv_bfloat16 g_Xq[(size_t)MTOT * KDIM];   // 64 MB
__device__ __align__(16) __nv_bfloat16 g_Wq[(size_t)NDIM * KDIM];   // 128 MB
__device__ float g_scale[MTOT];
__device__ float g_partial[2048];
__device__ float g_wscale;

// ---------------------------------------------------------------------------
// PTX helpers (portable compute_103 features only)
// ---------------------------------------------------------------------------
__device__ __forceinline__ uint32_t smem_u32(const void* p) {
    uint32_t a;
    asm("{ .reg .u64 t; cvta.to.shared.u64 t, %1; cvt.u32.u64 %0, t; }" : "=r"(a) : "l"(p));
    return a;
}

__device__ __forceinline__ void cp_async16(uint32_t dst, const void* src) {
    asm volatile("cp.async.cg.shared.global [%0], [%1], 16;" :: "r"(dst), "l"(src) : "memory");
}
__device__ __forceinline__ void cp_async_commit() {
    asm volatile("cp.async.commit_group;" ::: "memory");
}
template <int N>
__device__ __forceinline__ void cp_async_wait() {
    asm volatile("cp.async.wait_group %0;" :: "n"(N) : "memory");
}

__device__ __forceinline__ void ldmatrix_x4(uint32_t* r, uint32_t addr) {
    asm volatile("ldmatrix.sync.aligned.m8n8.x4.shared.b16 {%0,%1,%2,%3}, [%4];"
                 : "=r"(r[0]), "=r"(r[1]), "=r"(r[2]), "=r"(r[3]) : "r"(addr));
}

__device__ __forceinline__ void mma_bf16(float* d, const uint32_t* a, uint32_t b0, uint32_t b1) {
    asm volatile(
        "mma.sync.aligned.m16n8k16.row.col.f32.bf16.bf16.f32 "
        "{%0,%1,%2,%3}, {%4,%5,%6,%7}, {%8,%9}, {%0,%1,%2,%3};"
        : "+f"(d[0]), "+f"(d[1]), "+f"(d[2]), "+f"(d[3])
        : "r"(a[0]), "r"(a[1]), "r"(a[2]), "r"(a[3]), "r"(b0), "r"(b1));
}

// ---------------------------------------------------------------------------
// Kernel 1 (fused): blocks [0, MTOT) quantize X rows; blocks [MTOT, MTOT+2048)
// compute the deterministic partial sums of |W|. Independent work, one launch.
// ---------------------------------------------------------------------------
__global__ void __launch_bounds__(256) fused_qx_wabs_kernel(
    const float* __restrict__ x, const float* __restrict__ w) {
    __shared__ float red[256];
    __shared__ float wmax[8];
    __shared__ float s_scale;
    const int tid = threadIdx.x;

    if (blockIdx.x < MTOT) {
        // ---- per-token activation quantization -> bf16 integer (exact) ----
        const int row = blockIdx.x;
        const float4* xr = reinterpret_cast<const float4*>(x) + (size_t)row * (KDIM / 4);
        float4 v[4];
        float amax = 0.0f;
#pragma unroll
        for (int i = 0; i < 4; i++) {
            v[i] = xr[tid + i * 256];
            amax = fmaxf(amax, fmaxf(fmaxf(fabsf(v[i].x), fabsf(v[i].y)),
                                     fmaxf(fabsf(v[i].z), fabsf(v[i].w))));
        }
#pragma unroll
        for (int o = 16; o; o >>= 1) amax = fmaxf(amax, __shfl_xor_sync(0xffffffffu, amax, o));
        if ((tid & 31) == 0) wmax[tid >> 5] = amax;
        __syncthreads();
        if (tid == 0) {
            float m = wmax[0];
#pragma unroll
            for (int i = 1; i < 8; i++) m = fmaxf(m, wmax[i]);
            float sc = m / 127.0f;
            s_scale = sc;
            g_scale[row] = sc;
        }
        __syncthreads();
        const float d = s_scale + 1e-8f;
        ushort4* qr = reinterpret_cast<ushort4*>(g_Xq + (size_t)row * KDIM);
#pragma unroll
        for (int i = 0; i < 4; i++) {
            float q0 = fminf(fmaxf(rintf(v[i].x / d), -128.0f), 127.0f);
            float q1 = fminf(fmaxf(rintf(v[i].y / d), -128.0f), 127.0f);
            float q2 = fminf(fmaxf(rintf(v[i].z / d), -128.0f), 127.0f);
            float q3 = fminf(fmaxf(rintf(v[i].w / d), -128.0f), 127.0f);
            ushort4 u;
            u.x = __bfloat16_as_ushort(__float2bfloat16(q0));
            u.y = __bfloat16_as_ushort(__float2bfloat16(q1));
            u.z = __bfloat16_as_ushort(__float2bfloat16(q2));
            u.w = __bfloat16_as_ushort(__float2bfloat16(q3));
            qr[tid + i * 256] = u;
        }
    } else {
        // ---- deterministic partial sums of |W| (unchanged arithmetic) ----
        const int blk = blockIdx.x - MTOT;
        const float4* wp = reinterpret_cast<const float4*>(w);
        size_t base = (size_t)blk * 8192;
        float s = 0.0f;
#pragma unroll 8
        for (int i = 0; i < 32; i++) {
            float4 v = wp[base + tid + (size_t)i * 256];
            s += fabsf(v.x) + fabsf(v.y) + fabsf(v.z) + fabsf(v.w);
        }
        red[tid] = s;
        __syncthreads();
        for (int o = 128; o; o >>= 1) {
            if (tid < o) red[tid] += red[tid + o];
            __syncthreads();
        }
        if (tid == 0) g_partial[blk] = red[0];
    }
}

__global__ void __launch_bounds__(256) wabs_final_kernel() {
    __shared__ float red[256];
    const int tid = threadIdx.x;
    float s = 0.0f;
#pragma unroll
    for (int i = 0; i < 8; i++) s += g_partial[tid * 8 + i];
    red[tid] = s;
    __syncthreads();
    for (int o = 128; o; o >>= 1) {
        if (tid < o) red[tid] += red[tid + o];
        __syncthreads();
    }
    if (tid == 0) g_wscale = red[0] / (float)((size_t)NDIM * KDIM);
}

// ---------------------------------------------------------------------------
// Kernel 2c: ternary weight quantization -> bf16 {-1,0,1}
// ---------------------------------------------------------------------------
__global__ void __launch_bounds__(256) quant_w_kernel(const float* __restrict__ w) {
    const float thr = 0.5f * (g_wscale + 1e-8f);
    const int tid = threadIdx.x;
    const float4* wp = reinterpret_cast<const float4*>(w);
    ushort4* qp = reinterpret_cast<ushort4*>(g_Wq);
    const unsigned short POS = __bfloat16_as_ushort(__float2bfloat16(1.0f));
    const unsigned short NEG = __bfloat16_as_ushort(__float2bfloat16(-1.0f));
#pragma unroll
    for (int i = 0; i < 4; i++) {
        size_t j = (size_t)blockIdx.x * 1024 + tid + i * 256;
        float4 v = wp[j];
        ushort4 u;
        u.x = (fabsf(v.x) > thr) ? (v.x > 0.0f ? POS : NEG) : 0;
        u.y = (fabsf(v.y) > thr) ? (v.y > 0.0f ? POS : NEG) : 0;
        u.z = (fabsf(v.z) > thr) ? (v.z > 0.0f ? POS : NEG) : 0;
        u.w = (fabsf(v.w) > thr) ? (v.w > 0.0f ? POS : NEG) : 0;
        qp[j] = u;
    }
}

// ---------------------------------------------------------------------------
// Kernel 3: bf16 HMMA mma.sync GEMM — exact round-11 champion mainloop.
// CTA tile 128x128, 8 warps (2m x 4n), warp tile 64x32, 2 CTAs/SM.
// ---------------------------------------------------------------------------
__global__ void __launch_bounds__(GEMM_THREADS, 2) bitlinear_gemm_kernel(
    const float* __restrict__ bias, float* __restrict__ out) {
    extern __shared__ char smem[];
    const uint32_t sbase = smem_u32(smem);
    const int tid = threadIdx.x;

    // tile swizzle for L2 reuse
    const int pid = blockIdx.x;
    const int group = pid / (GROUP_M * NTILES_N);
    const int pig = pid % (GROUP_M * NTILES_N);
    const int pm = group * GROUP_M + (pig % GROUP_M);
    const int pn = pig / GROUP_M;
    const int m0 = pm * TILE_M;
    const int n0 = pn * TILE_N;

    const __nv_bfloat16* gA = g_Xq + (size_t)m0 * KDIM;
    const __nv_bfloat16* gB = g_Wq + (size_t)n0 * KDIM;

    // consumer (ldmatrix) lane constants
    const int wid = tid >> 5;
    const int lane = tid & 31;
    const int wm = (wid & 1) * 64;       // warp m offset (2 warps in m)
    const int wn = (wid >> 1) * 32;      // warp n offset (4 warps in n)
    const int lr = lane & 7;             // row within 8-row tile
    const int lt = lane >> 3;            // which of 4 ldmatrix tiles
    const int a_row = wm + (lt & 1) * 8 + lr;          // + mi*16
    const int a_colb = (lt >> 1) * 16;                 // + ks*32, then ^ (lr<<4)
    const int b_row = wn + (lt >> 1) * 8 + lr;         // + g*16
    const int b_colb = (lt & 1) * 16;                  // + ks*32, then ^ (lr<<4)
    const int lxor = lr << 4;

    float d[4][4][4];
#pragma unroll
    for (int mi = 0; mi < 4; mi++)
#pragma unroll
        for (int ni = 0; ni < 4; ni++)
#pragma unroll
            for (int r = 0; r < 4; r++) d[mi][ni][r] = 0.0f;

    // -------- producer: 2048 16B segments per stage, 8 per thread --------
    auto issue_stage = [&](int kc, int buf) {
        const uint32_t stage = sbase + buf * STAGE_BYTES;
        const int koff = kc * KC;   // element offset
#pragma unroll
        for (int i = 0; i < 8; i++) {
            const int idx = tid + i * GEMM_THREADS;
            const int j = idx & 1023;
            const int row = j >> 3;
            const int c = j & 7;
            const uint32_t swb = (uint32_t)((c << 4) ^ ((row & 7) << 4));
            if (idx < 1024) {
                cp_async16(stage + row * ROWB + swb,
                           gA + (size_t)row * KDIM + koff + (c << 3));
            } else {
                cp_async16(stage + STAGE_A_BYTES + row * ROWB + swb,
                           gB + (size_t)row * KDIM + koff + (c << 3));
            }
        }
    };

    // prologue: stages 0,1
    issue_stage(0, 0); cp_async_commit();
    issue_stage(1, 1); cp_async_commit();

    int buf = 0;
    for (int kc = 0; kc < NK; kc++) {
        cp_async_wait<1>();
        __syncthreads();

        // issue next-next stage (into buffer freed last iteration)
        if (kc + 2 < NK) {
            int nbuf = buf + 2; if (nbuf >= STAGES) nbuf -= STAGES;
            issue_stage(kc + 2, nbuf);
        }
        cp_async_commit();

        // compute on stage `buf`: KC=64 elems = 4 x k16
        const uint32_t sA = sbase + buf * STAGE_BYTES;
        const uint32_t sB = sA + STAGE_A_BYTES;
#pragma unroll
        for (int ks = 0; ks < 4; ks++) {
            uint32_t a[4][4];
            uint32_t b[2][4];
            // load order: operands for the FIRST MMAs first (a[0], b[0]),
            // so the initial mma chain's wait is minimized; remaining loads
            // complete under the MMA stream.
            {
                uint32_t addr = sA + (uint32_t)(a_row + 0 * 16) * ROWB
                              + (uint32_t)((a_colb + ks * 32) ^ lxor);
                ldmatrix_x4(a[0], addr);
            }
            {
                uint32_t addr = sB + (uint32_t)(b_row + 0 * 16) * ROWB
                              + (uint32_t)((b_colb + ks * 32) ^ lxor);
                ldmatrix_x4(b[0], addr);
            }
            {
                uint32_t addr = sB + (uint32_t)(b_row + 1 * 16) * ROWB
                              + (uint32_t)((b_colb + ks * 32) ^ lxor);
                ldmatrix_x4(b[1], addr);
            }
#pragma unroll
            for (int mi = 1; mi < 4; mi++) {
                uint32_t addr = sA + (uint32_t)(a_row + mi * 16) * ROWB
                              + (uint32_t)((a_colb + ks * 32) ^ lxor);
                ldmatrix_x4(a[mi], addr);
            }
#pragma unroll
            for (int mi = 0; mi < 4; mi++)
#pragma unroll
                for (int ni = 0; ni < 4; ni++)
                    mma_bf16(d[mi][ni], a[mi], b[ni >> 1][(ni & 1) * 2],
                             b[ni >> 1][(ni & 1) * 2 + 1]);
        }
        if (++buf == STAGES) buf = 0;
    }

    // -------- epilogue: out = scale[m]*acc + bias[n] --------
#pragma unroll
    for (int mi = 0; mi < 4; mi++) {
        const int m_lo = m0 + wm + mi * 16 + (lane >> 2);
        const float sc0 = g_scale[m_lo];
        const float sc1 = g_scale[m_lo + 8];
#pragma unroll
        for (int ni = 0; ni < 4; ni++) {
            const int n = n0 + wn + ni * 8 + 2 * (lane & 3);
            const float2 bs = *reinterpret_cast<const float2*>(bias + n);
            float2 v0, v1;
            v0.x = fmaf(sc0, d[mi][ni][0], bs.x);
            v0.y = fmaf(sc0, d[mi][ni][1], bs.y);
            v1.x = fmaf(sc1, d[mi][ni][2], bs.x);
            v1.y = fmaf(sc1, d[mi][ni][3], bs.y);
            *reinterpret_cast<float2*>(out + (size_t)m_lo * NDIM + n) = v0;
            *reinterpret_cast<float2*>(out + (size_t)(m_lo + 8) * NDIM + n) = v1;
        }
    }
}

// ---------------------------------------------------------------------------
// Launch
// ---------------------------------------------------------------------------
extern "C" void kernel_launch(void* const* d_in, const int* in_sizes, int n_in,
                              void* d_out, int out_size) {
    const float* x = (const float*)d_in[0];
    const float* w = (const float*)d_in[1];
    const float* bias = (const float*)d_in[2];
    float* out = (float*)d_out;

    cudaFuncSetAttribute(bitlinear_gemm_kernel,
                         cudaFuncAttributeMaxDynamicSharedMemorySize, SMEM_TOTAL);

    fused_qx_wabs_kernel<<<MTOT + 2048, 256>>>(x, w);
    wabs_final_kernel<<<1, 256>>>();
    quant_w_kernel<<<16384, 256>>>(w);

    const int grid = NTILES_M * NTILES_N;   // 64 * 128 = 8192
    bitlinear_gemm_kernel<<<grid, GEMM_THREADS, SMEM_TOTAL>>>(bias, out);
}